// round 11
// baseline (speedup 1.0000x reference)
#include <cuda_runtime.h>
#include <cuda_bf16.h>
#include <cstdint>

// BiLSTM persistent kernel, gates via warp-level mma.sync TF32 (3-pass split).
// 128 CTAs x 256 threads, software grid barriers. fc stays SIMT fp32 (proven).
// CTA gates tile 64(M) x 128(N); 8 warps 2x4; warp tile 32x32; K=768 in 24
// chunks of 32 (4 x k8 per chunk). Splits (tf32 hi/lo) precomputed so the
// mainloop is copy + fragment-LDS + mma only.
// R11 fix: A-fragment a1/a3 are at row groupID+8 (offset +288 words), not +16.

#define T_STEPS 255
#define BATCH   256
#define HID     512
#define VEC     256
#define G4H     2048
#define NCTA    128u

// dynamic smem: A 2x(64x36 f32)=18432B, B 2x(128x36 f32)=36864B -> 55296B.
// D staging (64x132 f32 = 33792B) and fc buffers reuse the same region.
#define SMA_B   0
#define SMB_B   18432
#define SM_SZ   55296

// ---------------- device globals (no allocations allowed) -------------------
__device__ __align__(16) float g_xs[2][256][256][256];        // [s][w][b][v]
__device__ __align__(16) float g_vs[2][2][BATCH][VEC];        // [s][dir][b][v]
__device__ __align__(16) float g_hs[2][2][2][2][BATCH][HID];  // [s][par][dir][dep]
__device__ __align__(16) float g_wihS[2][2][2][G4H][VEC];     // [s][dir][dep][4j+g][k]
__device__ __align__(16) float g_whhS[2][2][2][G4H][HID];
__device__ float g_biasR[2][2][G4H];
__device__ float g_h[2][2][2][BATCH][HID];                    // fp32 h for fc
__device__ float g_c[2][2][BATCH][HID];
__device__ unsigned g_count;
__device__ unsigned g_gen;

// ---------------- helpers ---------------------------------------------------
__device__ __forceinline__ float tf32_rna(float x)
{
    uint32_t u;
    asm("cvt.rna.tf32.f32 %0, %1;" : "=r"(u) : "f"(x));
    return __uint_as_float(u);
}

__device__ __forceinline__ void mma8(float* d, const uint32_t* a, uint32_t b0, uint32_t b1)
{
    asm volatile(
        "mma.sync.aligned.m16n8k8.row.col.f32.tf32.tf32.f32 "
        "{%0,%1,%2,%3}, {%4,%5,%6,%7}, {%8,%9}, {%0,%1,%2,%3};"
        : "+f"(d[0]), "+f"(d[1]), "+f"(d[2]), "+f"(d[3])
        : "r"(a[0]), "r"(a[1]), "r"(a[2]), "r"(a[3]), "r"(b0), "r"(b1));
}

// ---------------------------------------------------------------------------
// Prep: tf32 splits for weights and x, fold biases, zero state.
// ---------------------------------------------------------------------------
__global__ void prep_kernel(const float* __restrict__ x,
                            const float* __restrict__ wih_l, const float* __restrict__ whh_l,
                            const float* __restrict__ bih_l, const float* __restrict__ bhh_l,
                            const float* __restrict__ wih_r, const float* __restrict__ whh_r,
                            const float* __restrict__ bih_r, const float* __restrict__ bhh_r)
{
    const unsigned tid = blockIdx.x * blockDim.x + threadIdx.x;
    const unsigned nth = gridDim.x * blockDim.x;
    if (tid == 0) { g_count = 0u; g_gen = 0u; }

    // wih splits (gate-interleaved rows): 2^21 elements
    for (unsigned i = tid; i < (1u << 21); i += nth) {
        unsigned k  = i & 255u;
        unsigned r  = (i >> 8) & 2047u;
        unsigned d  = (i >> 19) & 1u;
        unsigned dr = (i >> 20) & 1u;
        unsigned j = r >> 2, g = r & 3u;
        const float* src = dr ? wih_r : wih_l;
        float w = src[((size_t)d * G4H + g * HID + j) * VEC + k];
        float hi = tf32_rna(w);
        g_wihS[0][dr][d][r][k] = hi;
        g_wihS[1][dr][d][r][k] = tf32_rna(w - hi);
    }
    // whh splits: 2^22
    for (unsigned i = tid; i < (1u << 22); i += nth) {
        unsigned k  = i & 511u;
        unsigned r  = (i >> 9) & 2047u;
        unsigned d  = (i >> 20) & 1u;
        unsigned dr = (i >> 21) & 1u;
        unsigned j = r >> 2, g = r & 3u;
        const float* src = dr ? whh_r : whh_l;
        float w = src[((size_t)d * G4H + g * HID + j) * HID + k];
        float hi = tf32_rna(w);
        g_whhS[0][dr][d][r][k] = hi;
        g_whhS[1][dr][d][r][k] = tf32_rna(w - hi);
    }
    // x splits: 2^24, dst-linear [s][w][b][v]
    for (unsigned i = tid; i < (1u << 24); i += nth) {
        unsigned v = i & 255u, b = (i >> 8) & 255u, w = i >> 16;
        float xv = x[(((size_t)b << 8) | w) << 8 | v];
        float hi = tf32_rna(xv);
        g_xs[0][w][b][v] = hi;
        g_xs[1][w][b][v] = tf32_rna(xv - hi);
    }
    // biasR
    for (unsigned i = tid; i < 8192u; i += nth) {
        unsigned r  = i & 2047u;
        unsigned d  = (i >> 11) & 1u;
        unsigned dr = (i >> 12) & 1u;
        unsigned j = r >> 2, g = r & 3u;
        const float* bi = dr ? bih_r : bih_l;
        const float* bh = dr ? bhh_r : bhh_l;
        ((float*)g_biasR)[i] = bi[d * G4H + g * HID + j] + bh[d * G4H + g * HID + j];
    }
    // zero: g_hs (2^21), g_h (2^20), g_c (2^19), g_vs (2^18)
    for (unsigned i = tid; i < (1u << 21); i += nth) ((float*)g_hs)[i] = 0.f;
    for (unsigned i = tid; i < (1u << 20); i += nth) ((float*)g_h)[i] = 0.f;
    for (unsigned i = tid; i < (1u << 19); i += nth) ((float*)g_c)[i] = 0.f;
    for (unsigned i = tid; i < (1u << 18); i += nth) ((float*)g_vs)[i] = 0.f;
}

// ---------------------------------------------------------------------------
__device__ __forceinline__ void grid_bar(unsigned* s_gen)
{
    __syncthreads();
    if (threadIdx.x == 0) {
        unsigned my = ++(*s_gen);
        __threadfence();
        if (atomicAdd(&g_count, 1u) == NCTA - 1u) {
            g_count = 0u;
            __threadfence();
            atomicAdd(&g_gen, 1u);
        } else {
            while (*((volatile unsigned*)&g_gen) < my) { __nanosleep(32); }
        }
        __threadfence();
    }
    __syncthreads();
}

// ---------------------------------------------------------------------------
// Gates: CTA tile 64x128, K=768 (8 chunks x|v part + 16 chunks h part).
// ---------------------------------------------------------------------------
__device__ void gates_mma(char* dyn, int tid,
                          const float* __restrict__ Ax0, const float* __restrict__ Ax1,
                          long ldax,
                          const float* __restrict__ Ah0, const float* __restrict__ Ah1,
                          const float* __restrict__ Bi0, const float* __restrict__ Bi1,
                          const float* __restrict__ Bh0, const float* __restrict__ Bh1,
                          const float* __restrict__ bias,
                          float* __restrict__ hout, float* __restrict__ cst,
                          float* __restrict__ hs0, float* __restrict__ hs1,
                          int gbm, int gbn)
{
    const int wid = tid >> 5, lid = tid & 31;
    const int g = lid >> 2, t = lid & 3;
    const int wm = (wid & 1) << 5;     // warp row base (0/32)
    const int wn = (wid >> 1) << 5;    // warp col base (0..96)

    float d[2][4][4];
#pragma unroll
    for (int a = 0; a < 2; ++a)
#pragma unroll
        for (int b = 0; b < 4; ++b)
#pragma unroll
            for (int c = 0; c < 4; ++c) d[a][b][c] = 0.f;

    uint4 pa[4], pb[8];

    // chunk c: c<8 -> x|v segment (koff=c*32), else h segment (koff=(c-8)*32)
    auto ldA = [&](int c, uint4* r) {
        const bool xp = c < 8;
        const int koff = xp ? c * 32 : (c - 8) * 32;
        const long lda = xp ? ldax : (long)HID;
#pragma unroll
        for (int i = 0; i < 4; ++i) {
            unsigned u = tid + (i << 8), s = u >> 9, rem = u & 511u;
            unsigned row = rem >> 3, q = rem & 7u;
            const float* base = xp ? (s ? Ax1 : Ax0) : (s ? Ah1 : Ah0);
            r[i] = *(const uint4*)(base + (long)row * lda + koff + q * 4);
        }
    };
    auto ldB = [&](int c, uint4* r) {
        const bool xp = c < 8;
        const int koff = xp ? c * 32 : (c - 8) * 32;
        const long ldb = xp ? (long)VEC : (long)HID;
#pragma unroll
        for (int i = 0; i < 8; ++i) {
            unsigned u = tid + (i << 8), s = u >> 10, rem = u & 1023u;
            unsigned row = rem >> 3, q = rem & 7u;
            const float* base = xp ? (s ? Bi1 : Bi0) : (s ? Bh1 : Bh0);
            r[i] = *(const uint4*)(base + (long)row * ldb + koff + q * 4);
        }
    };

    ldA(0, pa); ldB(0, pb);

    for (int c = 0; c < 24; ++c) {
        __syncthreads();   // smem free of previous chunk/phase readers
#pragma unroll
        for (int i = 0; i < 4; ++i) {
            unsigned u = tid + (i << 8), s = u >> 9, rem = u & 511u;
            unsigned row = rem >> 3, q = rem & 7u;
            *(uint4*)(dyn + SMA_B + s * 9216 + row * 144 + q * 16) = pa[i];
        }
#pragma unroll
        for (int i = 0; i < 8; ++i) {
            unsigned u = tid + (i << 8), s = u >> 10, rem = u & 1023u;
            unsigned row = rem >> 3, q = rem & 7u;
            *(uint4*)(dyn + SMB_B + s * 18432 + row * 144 + q * 16) = pb[i];
        }
        __syncthreads();

        if (c < 23) { ldA(c + 1, pa); ldB(c + 1, pb); }   // overlap L2 with mma

        const uint32_t* sAw = (const uint32_t*)(dyn + SMA_B);
        const uint32_t* sBw = (const uint32_t*)(dyn + SMB_B);

#pragma unroll
        for (int kq = 0; kq < 4; ++kq) {
            uint32_t af[2][2][4];     // [split][mi][reg]
#pragma unroll
            for (int s = 0; s < 2; ++s)
#pragma unroll
                for (int mi = 0; mi < 2; ++mi) {
                    int ro = s * 2304 + (wm + mi * 16 + g) * 36 + kq * 8 + t;
                    af[s][mi][0] = sAw[ro];
                    af[s][mi][1] = sAw[ro + 288];   // row groupID+8 (8*36 words)
                    af[s][mi][2] = sAw[ro + 4];
                    af[s][mi][3] = sAw[ro + 292];
                }
#pragma unroll
            for (int ni = 0; ni < 4; ++ni) {
                int bo = (wn + ni * 8 + g) * 36 + kq * 8 + t;
                uint32_t b0h = sBw[bo],        b1h = sBw[bo + 4];
                uint32_t b0l = sBw[bo + 4608], b1l = sBw[bo + 4608 + 4];
#pragma unroll
                for (int mi = 0; mi < 2; ++mi) {
                    mma8(d[mi][ni], af[0][mi], b0h, b1h);   // hi*hi
                    mma8(d[mi][ni], af[0][mi], b0l, b1l);   // hi*lo
                    mma8(d[mi][ni], af[1][mi], b0h, b1h);   // lo*hi
                }
            }
        }
    }

    // Stage D -> smem (reuse A/B region), then vectorized cell epilogue.
    __syncthreads();
    float* sD = (float*)dyn;          // [64][132]
#pragma unroll
    for (int mi = 0; mi < 2; ++mi)
#pragma unroll
        for (int ni = 0; ni < 4; ++ni) {
            int row = wm + mi * 16 + g;
            int col = wn + ni * 8 + 2 * t;
            *(float2*)&sD[row * 132 + col]       = make_float2(d[mi][ni][0], d[mi][ni][1]);
            *(float2*)&sD[(row + 8) * 132 + col] = make_float2(d[mi][ni][2], d[mi][ni][3]);
        }
    __syncthreads();

    {
        const int r  = tid >> 2;            // 0..63
        const int ub = (tid & 3) << 3;      // 0,8,16,24 (unit offset)
        const int m  = gbm + r;
        const long cb = (long)m * HID + (gbn >> 2) + ub;

        float4 co0 = *(const float4*)(cst + cb);
        float4 co1 = *(const float4*)(cst + cb + 4);
        float cold[8] = {co0.x, co0.y, co0.z, co0.w, co1.x, co1.y, co1.z, co1.w};
        float cn8[8], hn8[8], hh8[8], hl8[8];

#pragma unroll
        for (int jj = 0; jj < 8; ++jj) {
            const float* q = &sD[r * 132 + (ub + jj) * 4];
            const float* bq = &bias[gbn + (ub + jj) * 4];
            float ig = q[0] + bq[0];
            float fg = q[1] + bq[1];
            float gg = q[2] + bq[2];
            float og = q[3] + bq[3];
            float si = 1.f / (1.f + __expf(-ig));
            float sf = 1.f / (1.f + __expf(-fg));
            float so = 1.f / (1.f + __expf(-og));
            float tg = tanhf(gg);
            float cn = sf * cold[jj] + si * tg;
            float hn = so * tanhf(cn);
            cn8[jj] = cn; hn8[jj] = hn;
            float hi = tf32_rna(hn);
            hh8[jj] = hi;
            hl8[jj] = tf32_rna(hn - hi);
        }
        *(float4*)(cst + cb)      = make_float4(cn8[0], cn8[1], cn8[2], cn8[3]);
        *(float4*)(cst + cb + 4)  = make_float4(cn8[4], cn8[5], cn8[6], cn8[7]);
        *(float4*)(hout + cb)     = make_float4(hn8[0], hn8[1], hn8[2], hn8[3]);
        *(float4*)(hout + cb + 4) = make_float4(hn8[4], hn8[5], hn8[6], hn8[7]);
        *(float4*)(hs0 + cb)      = make_float4(hh8[0], hh8[1], hh8[2], hh8[3]);
        *(float4*)(hs0 + cb + 4)  = make_float4(hh8[4], hh8[5], hh8[6], hh8[7]);
        *(float4*)(hs1 + cb)      = make_float4(hl8[0], hl8[1], hl8[2], hl8[3]);
        *(float4*)(hs1 + cb + 4)  = make_float4(hl8[4], hl8[5], hl8[6], hl8[7]);
    }
}

// ---------------------------------------------------------------------------
// FC tile: 32(M) x 32(N), K=512, 256 threads, 2x2 (R4/R8-identical math).
// vmode: also emit tf32 hi/lo splits of v.
// ---------------------------------------------------------------------------
__device__ void do_fc(float* __restrict__ sA, float* __restrict__ sB, int tid,
                      const float* __restrict__ hin, const float* __restrict__ Wf,
                      const float* __restrict__ bf,
                      float* __restrict__ outp, long ldo, int bm, int bn,
                      int vmode, int dir)
{
    const int r2 = (tid >> 4) << 1;
    const int c2 = (tid & 15) << 1;
    float acc00 = 0.f, acc01 = 0.f, acc10 = 0.f, acc11 = 0.f;

    const int r = tid >> 3; const int kq = (tid & 7) << 2;
    float4 pa = *(const float4*)(hin + (long)(bm + r) * HID + kq);
    float4 pb = *(const float4*)(Wf + (long)(bn + r) * HID + kq);

    for (int k0 = 0; k0 < HID; k0 += 32) {
        __syncthreads();
        sA[(kq + 0) * 68 + r] = pa.x; sA[(kq + 1) * 68 + r] = pa.y;
        sA[(kq + 2) * 68 + r] = pa.z; sA[(kq + 3) * 68 + r] = pa.w;
        sB[(kq + 0) * 136 + r] = pb.x; sB[(kq + 1) * 136 + r] = pb.y;
        sB[(kq + 2) * 136 + r] = pb.z; sB[(kq + 3) * 136 + r] = pb.w;
        __syncthreads();

        int kn = k0 + 32;
        if (kn < HID) {
            pa = *(const float4*)(hin + (long)(bm + r) * HID + kn + kq);
            pb = *(const float4*)(Wf + (long)(bn + r) * HID + kn + kq);
        }

#pragma unroll
        for (int kk = 0; kk < 32; ++kk) {
            float a0 = sA[kk * 68 + r2], a1 = sA[kk * 68 + r2 + 1];
            float b0 = sB[kk * 136 + c2], b1 = sB[kk * 136 + c2 + 1];
            acc00 = fmaf(a0, b0, acc00); acc01 = fmaf(a0, b1, acc01);
            acc10 = fmaf(a1, b0, acc10); acc11 = fmaf(a1, b1, acc11);
        }
    }

    float o00 = acc00 + bf[bn + c2], o01 = acc01 + bf[bn + c2 + 1];
    float o10 = acc10 + bf[bn + c2], o11 = acc11 + bf[bn + c2 + 1];

    if (vmode) {
#pragma unroll
        for (int rr = 0; rr < 2; ++rr) {
            float v0 = rr ? o10 : o00, v1 = rr ? o11 : o01;
            float h0 = tf32_rna(v0), h1 = tf32_rna(v1);
            long off = (long)(bm + r2 + rr) * VEC + bn + c2;
            *(float2*)(&g_vs[0][dir][0][0] + off) = make_float2(h0, h1);
            *(float2*)(&g_vs[1][dir][0][0] + off) = make_float2(tf32_rna(v0 - h0), tf32_rna(v1 - h1));
        }
    } else {
        *(float2*)(outp + (long)(bm + r2) * ldo + bn + c2)     = make_float2(o00, o01);
        *(float2*)(outp + (long)(bm + r2 + 1) * ldo + bn + c2) = make_float2(o10, o11);
    }
}

// ---------------------------------------------------------------------------
__global__ __launch_bounds__(256, 1) void bilstm_kernel(
    const float* __restrict__ wfc_l, const float* __restrict__ wfc_r,
    const float* __restrict__ bfc_l, const float* __restrict__ bfc_r,
    float* __restrict__ out)
{
    extern __shared__ __align__(16) char dyn[];
    __shared__ unsigned s_gen;

    const int tid = threadIdx.x;
    const int cid = blockIdx.x;
    const int dir = cid >> 6;
    const int idx = cid & 63;
    const int gbm = (idx >> 4) << 6;   // 4 M tiles of 64
    const int gbn = (idx & 15) << 7;   // 16 N tiles of 128
    const int fbm = (idx >> 3) << 5;   // fc 8x8 tiles of 32
    const int fbn = (idx & 7) << 5;

    float* fcA = (float*)dyn;
    float* fcB = fcA + 32 * 68;

    if (tid == 0) s_gen = 0u;
    __syncthreads();

    const float* wfc = dir ? wfc_r : wfc_l;
    const float* bfc = dir ? bfc_r : bfc_l;

    for (int t = 0; t < T_STEPS; ++t) {
        const int p = t & 1;

        {   // gates depth 0 (A = x | h0)
            const int step = dir ? (T_STEPS - t) : t;
            gates_mma(dyn, tid,
                      &g_xs[0][step][gbm][0], &g_xs[1][step][gbm][0], (long)VEC,
                      &g_hs[0][p][dir][0][gbm][0], &g_hs[1][p][dir][0][gbm][0],
                      &g_wihS[0][dir][0][gbn][0], &g_wihS[1][dir][0][gbn][0],
                      &g_whhS[0][dir][0][gbn][0], &g_whhS[1][dir][0][gbn][0],
                      &g_biasR[dir][0][0],
                      &g_h[p ^ 1][dir][0][0][0], &g_c[dir][0][0][0],
                      &g_hs[0][p ^ 1][dir][0][0][0], &g_hs[1][p ^ 1][dir][0][0][0],
                      gbm, gbn);
        }
        grid_bar(&s_gen);

        do_fc(fcA, fcB, tid, &g_h[p ^ 1][dir][0][0][0], wfc, bfc,
              nullptr, 0, fbm, fbn, 1, dir);
        grid_bar(&s_gen);

        {   // gates depth 1 (A = v | h1)
            gates_mma(dyn, tid,
                      &g_vs[0][dir][gbm][0], &g_vs[1][dir][gbm][0], (long)VEC,
                      &g_hs[0][p][dir][1][gbm][0], &g_hs[1][p][dir][1][gbm][0],
                      &g_wihS[0][dir][1][gbn][0], &g_wihS[1][dir][1][gbn][0],
                      &g_whhS[0][dir][1][gbn][0], &g_whhS[1][dir][1][gbn][0],
                      &g_biasR[dir][1][0],
                      &g_h[p ^ 1][dir][1][0][0], &g_c[dir][1][0][0],
                      &g_hs[0][p ^ 1][dir][1][0][0], &g_hs[1][p ^ 1][dir][1][0][0],
                      gbm, gbn);
        }
        grid_bar(&s_gen);

        {   // fc depth 1 -> output
            const int tout = dir ? (T_STEPS + t) : t;
            do_fc(fcA, fcB, tid, &g_h[p ^ 1][dir][1][0][0],
                  wfc + (long)VEC * HID, bfc + VEC,
                  out + (long)tout * VEC, (long)2 * T_STEPS * VEC, fbm, fbn, 0, dir);
        }
        // no barrier: gates0(t+1) is independent of fc1(t).
    }
}

// ---------------------------------------------------------------------------
extern "C" void kernel_launch(void* const* d_in, const int* in_sizes, int n_in,
                              void* d_out, int out_size)
{
    const float* x     = (const float*)d_in[0];
    const float* wih_l = (const float*)d_in[1];
    const float* whh_l = (const float*)d_in[2];
    const float* bih_l = (const float*)d_in[3];
    const float* bhh_l = (const float*)d_in[4];
    const float* wfc_l = (const float*)d_in[5];
    const float* bfc_l = (const float*)d_in[6];
    const float* wih_r = (const float*)d_in[7];
    const float* whh_r = (const float*)d_in[8];
    const float* bih_r = (const float*)d_in[9];
    const float* bhh_r = (const float*)d_in[10];
    const float* wfc_r = (const float*)d_in[11];
    const float* bfc_r = (const float*)d_in[12];
    float* out = (float*)d_out;

    cudaFuncSetAttribute(bilstm_kernel,
                         cudaFuncAttributeMaxDynamicSharedMemorySize, SM_SZ);

    prep_kernel<<<512, 256>>>(x, wih_l, whh_l, bih_l, bhh_l,
                              wih_r, whh_r, bih_r, bhh_r);
    bilstm_kernel<<<NCTA, 256, SM_SZ>>>(wfc_l, wfc_r, bfc_l, bfc_r, out);
}

// round 16
// speedup vs baseline: 1.6781x; 1.6781x over previous
#include <cuda_runtime.h>
#include <cuda_bf16.h>
#include <cstdint>

// BiLSTM persistent kernel, gates via warp mma.sync TF32 (3-pass split).
// R13 = R12 with the prep zero-loop overruns fixed (g_hf: 2^21, g_vf: 2^18).
// Fragment-ready gmem layouts; staging is verbatim uint4 copies; fragment
// reads are LDS.128, conflict-free. Epilogues write h/v in fragment order.

#define T_STEPS 255
#define BATCH   256
#define HID     512
#define VEC     256
#define G4H     2048
#define NCTA    128u

#define SMA_B   0          // A: 4kq x 4mb x 2s x 32lane x 16B = 16384
#define SMB_B   16384      // B: 4kq x 16nb x 32lane x 16B   = 32768
#define SM_SZ   49152

// ---------------- device globals --------------------------------------------
// A-frag arrays: [..][c][kq][MB(16)][s(2)][lane(32)][w(4)]
__device__ __align__(16) float g_xf[256][8][4][16][2][32][4];
__device__ __align__(16) float g_vf[2][8][4][16][2][32][4];
__device__ __align__(16) float g_hf[2][2][2][16][4][16][2][32][4]; // [par][dir][dep]...
// B-frag arrays: [..][c][kq][nb(256)][lane(32)][w(4)]  (w packs hi/lo)
__device__ __align__(16) float g_wihF[2][2][8][4][256][32][4];
__device__ __align__(16) float g_whhF[2][2][16][4][256][32][4];
__device__ float g_biasR[2][2][G4H];
__device__ float g_h[2][2][2][BATCH][HID];   // fp32 h for fc
__device__ float g_c[2][2][BATCH][HID];
__device__ unsigned g_count;
__device__ unsigned g_gen;

// ---------------- helpers ---------------------------------------------------
__device__ __forceinline__ float tf32_rna(float x)
{
    uint32_t u;
    asm("cvt.rna.tf32.f32 %0, %1;" : "=r"(u) : "f"(x));
    return __uint_as_float(u);
}

__device__ __forceinline__ void mma8(float* d, const uint32_t* a, uint32_t b0, uint32_t b1)
{
    asm volatile(
        "mma.sync.aligned.m16n8k8.row.col.f32.tf32.tf32.f32 "
        "{%0,%1,%2,%3}, {%4,%5,%6,%7}, {%8,%9}, {%0,%1,%2,%3};"
        : "+f"(d[0]), "+f"(d[1]), "+f"(d[2]), "+f"(d[3])
        : "r"(a[0]), "r"(a[1]), "r"(a[2]), "r"(a[3]), "r"(b0), "r"(b1));
}

// ---------------------------------------------------------------------------
// Prep: build fragment-ordered splits for weights and x; biases; zero state.
// ---------------------------------------------------------------------------
__global__ void prep_kernel(const float* __restrict__ x,
                            const float* __restrict__ wih_l, const float* __restrict__ whh_l,
                            const float* __restrict__ bih_l, const float* __restrict__ bhh_l,
                            const float* __restrict__ wih_r, const float* __restrict__ whh_r,
                            const float* __restrict__ bih_r, const float* __restrict__ bhh_r)
{
    const unsigned tid = blockIdx.x * blockDim.x + threadIdx.x;
    const unsigned nth = gridDim.x * blockDim.x;
    if (tid == 0) { g_count = 0u; g_gen = 0u; }

    // wihF: 2^21 elements
    for (unsigned i = tid; i < (1u << 21); i += nth) {
        unsigned k  = i & 255u;
        unsigned n  = (i >> 8) & 2047u;
        unsigned d  = (i >> 19) & 1u;
        unsigned dr = (i >> 20) & 1u;
        unsigned j = n >> 2, gate = n & 3u;
        const float* src = dr ? wih_r : wih_l;
        float w = src[((size_t)d * G4H + gate * HID + j) * VEC + k];
        float hi = tf32_rna(w), lo = tf32_rna(w - hi);
        unsigned nb = n >> 3, g = n & 7u;
        unsigned c = k >> 5, kq = (k >> 3) & 3u, t = k & 3u, kh = (k >> 2) & 1u;
        g_wihF[dr][d][c][kq][nb][g * 4 + t][kh]     = hi;
        g_wihF[dr][d][c][kq][nb][g * 4 + t][2 + kh] = lo;
    }
    // whhF: 2^22
    for (unsigned i = tid; i < (1u << 22); i += nth) {
        unsigned k  = i & 511u;
        unsigned n  = (i >> 9) & 2047u;
        unsigned d  = (i >> 20) & 1u;
        unsigned dr = (i >> 21) & 1u;
        unsigned j = n >> 2, gate = n & 3u;
        const float* src = dr ? whh_r : whh_l;
        float w = src[((size_t)d * G4H + gate * HID + j) * HID + k];
        float hi = tf32_rna(w), lo = tf32_rna(w - hi);
        unsigned nb = n >> 3, g = n & 7u;
        unsigned c = k >> 5, kq = (k >> 3) & 3u, t = k & 3u, kh = (k >> 2) & 1u;
        g_whhF[dr][d][c][kq][nb][g * 4 + t][kh]     = hi;
        g_whhF[dr][d][c][kq][nb][g * 4 + t][2 + kh] = lo;
    }
    // xf: 2^24  (x[b][w][v] -> A-frag of step w: row=b, k=v)
    for (unsigned i = tid; i < (1u << 24); i += nth) {
        unsigned v = i & 255u, b = (i >> 8) & 255u, w = i >> 16;
        float xv = x[(((size_t)b << 8) | w) << 8 | v];
        float hi = tf32_rna(xv), lo = tf32_rna(xv - hi);
        unsigned MB = b >> 4, g = (b & 15u) & 7u, hf = (b >> 3) & 1u;
        unsigned c = v >> 5, kq = (v >> 3) & 3u, t = v & 3u, kh = (v >> 2) & 1u;
        g_xf[w][c][kq][MB][0][g * 4 + t][kh * 2 + hf] = hi;
        g_xf[w][c][kq][MB][1][g * 4 + t][kh * 2 + hf] = lo;
    }
    // biasR
    for (unsigned i = tid; i < 8192u; i += nth) {
        unsigned r  = i & 2047u;
        unsigned d  = (i >> 11) & 1u;
        unsigned dr = (i >> 12) & 1u;
        unsigned j = r >> 2, gate = r & 3u;
        const float* bi = dr ? bih_r : bih_l;
        const float* bh = dr ? bhh_r : bhh_l;
        ((float*)g_biasR)[i] = bi[d * G4H + gate * HID + j] + bh[d * G4H + gate * HID + j];
    }
    // zero (exact sizes): g_hf 2^21, g_vf 2^18, g_h 2^20, g_c 2^19
    for (unsigned i = tid; i < (1u << 21); i += nth) ((float*)g_hf)[i] = 0.f;
    for (unsigned i = tid; i < (1u << 18); i += nth) ((float*)g_vf)[i] = 0.f;
    for (unsigned i = tid; i < (1u << 20); i += nth) ((float*)g_h)[i] = 0.f;
    for (unsigned i = tid; i < (1u << 19); i += nth) ((float*)g_c)[i] = 0.f;
}

// ---------------------------------------------------------------------------
__device__ __forceinline__ void grid_bar(unsigned* s_gen)
{
    __syncthreads();
    if (threadIdx.x == 0) {
        unsigned my = ++(*s_gen);
        __threadfence();
        if (atomicAdd(&g_count, 1u) == NCTA - 1u) {
            g_count = 0u;
            __threadfence();
            atomicAdd(&g_gen, 1u);
        } else {
            while (*((volatile unsigned*)&g_gen) < my) { __nanosleep(32); }
        }
        __threadfence();
    }
    __syncthreads();
}

// ---------------------------------------------------------------------------
// Gates: CTA 64x128, K=768 = 8 chunks (x|v) + 16 chunks (h), frag-ready data.
// ---------------------------------------------------------------------------
__device__ void gates_mma(char* dyn, int tid,
                          const float* __restrict__ Axf, const float* __restrict__ Ahf,
                          const float* __restrict__ Bif, const float* __restrict__ Bhf,
                          const float* __restrict__ bias,
                          float* __restrict__ hout, float* __restrict__ cst,
                          float* __restrict__ hfw,
                          int gbm, int gbn)
{
    const int wid = tid >> 5, lid = tid & 31;
    const int mb0 = (wid & 1) << 1;   // local m16 blocks mb0, mb0+1
    const int nb0 = (wid >> 1) << 2;  // local n8 blocks nb0..nb0+3

    float d[2][4][4];
#pragma unroll
    for (int a = 0; a < 2; ++a)
#pragma unroll
        for (int b = 0; b < 4; ++b)
#pragma unroll
            for (int c = 0; c < 4; ++c) d[a][b][c] = 0.f;

    uint4 pa[4], pb[8];

    auto ldA = [&](int c, uint4* r) {
        const float* Ab = (c < 8) ? (Axf + (long)c * 16384)
                                  : (Ahf + (long)(c - 8) * 16384);
#pragma unroll
        for (int i = 0; i < 4; ++i) {
            int f = tid + (i << 8);            // 0..1023
            int kq = f >> 8, rem = f & 255;
            r[i] = *(const uint4*)(Ab + (long)kq * 4096 + rem * 4);
        }
    };
    auto ldB = [&](int c, uint4* r) {
        const float* Bb = (c < 8) ? (Bif + (long)c * 131072)
                                  : (Bhf + (long)(c - 8) * 131072);
#pragma unroll
        for (int i = 0; i < 8; ++i) {
            int f = tid + (i << 8);            // 0..2047
            int kq = f >> 9, rem = f & 511;
            r[i] = *(const uint4*)(Bb + (long)kq * 32768 + rem * 4);
        }
    };

    ldA(0, pa); ldB(0, pb);

    for (int c = 0; c < 24; ++c) {
        __syncthreads();   // previous chunk/phase consumers done with smem
#pragma unroll
        for (int i = 0; i < 4; ++i) {
            int f = tid + (i << 8);
            *(uint4*)(dyn + SMA_B + f * 16) = pa[i];
        }
#pragma unroll
        for (int i = 0; i < 8; ++i) {
            int f = tid + (i << 8);
            *(uint4*)(dyn + SMB_B + f * 16) = pb[i];
        }
        __syncthreads();

        if (c < 23) { ldA(c + 1, pa); ldB(c + 1, pb); }   // overlap with mma

        const float* sA = (const float*)(dyn + SMA_B);
        const float* sB = (const float*)(dyn + SMB_B);

#pragma unroll
        for (int kq = 0; kq < 4; ++kq) {
            uint4 aH[2], aL[2], bF[4];
#pragma unroll
            for (int mi = 0; mi < 2; ++mi) {
                int base = (((kq * 4 + mb0 + mi) * 2) * 32 + lid) * 4;
                aH[mi] = *(const uint4*)(sA + base);
                aL[mi] = *(const uint4*)(sA + base + 128);
            }
#pragma unroll
            for (int ni = 0; ni < 4; ++ni)
                bF[ni] = *(const uint4*)(sB + ((kq * 16 + nb0 + ni) * 32 + lid) * 4);

            // pass-major: 8 independent accumulators between reuses
#pragma unroll
            for (int ni = 0; ni < 4; ++ni)
#pragma unroll
                for (int mi = 0; mi < 2; ++mi)
                    mma8(d[mi][ni], (const uint32_t*)&aH[mi], bF[ni].x, bF[ni].y);
#pragma unroll
            for (int ni = 0; ni < 4; ++ni)
#pragma unroll
                for (int mi = 0; mi < 2; ++mi)
                    mma8(d[mi][ni], (const uint32_t*)&aH[mi], bF[ni].z, bF[ni].w);
#pragma unroll
            for (int ni = 0; ni < 4; ++ni)
#pragma unroll
                for (int mi = 0; mi < 2; ++mi)
                    mma8(d[mi][ni], (const uint32_t*)&aL[mi], bF[ni].x, bF[ni].y);
        }
    }

    // Stage D -> smem, then cell epilogue (identical math to R11).
    __syncthreads();
    float* sD = (float*)dyn;          // [64][132]
    {
        const int g = lid >> 2, t = lid & 3;
        const int wm = (wid & 1) << 5, wn = (wid >> 1) << 5;
#pragma unroll
        for (int mi = 0; mi < 2; ++mi)
#pragma unroll
            for (int ni = 0; ni < 4; ++ni) {
                int row = wm + mi * 16 + g;
                int col = wn + ni * 8 + 2 * t;
                *(float2*)&sD[row * 132 + col]       = make_float2(d[mi][ni][0], d[mi][ni][1]);
                *(float2*)&sD[(row + 8) * 132 + col] = make_float2(d[mi][ni][2], d[mi][ni][3]);
            }
    }
    __syncthreads();

    {
        const int r  = tid >> 2;            // 0..63
        const int ub = (tid & 3) << 3;      // 0,8,16,24
        const int m  = gbm + r;
        const int u0 = (gbn >> 2) + ub;     // 8-aligned hidden-unit base
        const long cb = (long)m * HID + u0;

        float4 co0 = *(const float4*)(cst + cb);
        float4 co1 = *(const float4*)(cst + cb + 4);
        float cold[8] = {co0.x, co0.y, co0.z, co0.w, co1.x, co1.y, co1.z, co1.w};
        float cn8[8], hn8[8];

        const int MB = m >> 4, gh = (m & 15) & 7, hf = (m >> 3) & 1;
        const long ob = (((long)((u0 >> 5) * 4 + ((u0 >> 3) & 3)) * 16 + MB) * 2) * 128;

#pragma unroll
        for (int jj = 0; jj < 8; ++jj) {
            const float* q  = &sD[r * 132 + (ub + jj) * 4];
            const float* bq = &bias[gbn + (ub + jj) * 4];
            float ig = q[0] + bq[0];
            float fg = q[1] + bq[1];
            float gg = q[2] + bq[2];
            float og = q[3] + bq[3];
            float si = 1.f / (1.f + __expf(-ig));
            float sf = 1.f / (1.f + __expf(-fg));
            float so = 1.f / (1.f + __expf(-og));
            float tg = tanhf(gg);
            float cn = sf * cold[jj] + si * tg;
            float hn = so * tanhf(cn);
            cn8[jj] = cn; hn8[jj] = hn;

            float hi = tf32_rna(hn);
            int kh = jj >> 2, t = jj & 3;
            long fo = ob + (gh * 4 + t) * 4 + kh * 2 + hf;
            hfw[fo]       = hi;
            hfw[fo + 128] = tf32_rna(hn - hi);
        }
        *(float4*)(cst + cb)      = make_float4(cn8[0], cn8[1], cn8[2], cn8[3]);
        *(float4*)(cst + cb + 4)  = make_float4(cn8[4], cn8[5], cn8[6], cn8[7]);
        *(float4*)(hout + cb)     = make_float4(hn8[0], hn8[1], hn8[2], hn8[3]);
        *(float4*)(hout + cb + 4) = make_float4(hn8[4], hn8[5], hn8[6], hn8[7]);
    }
}

// ---------------------------------------------------------------------------
// FC tile: 32x32, K=512, SIMT fp32 (R4/R11-identical math).
// vmode: emit v in fragment order (hi/lo) to vfw.
// ---------------------------------------------------------------------------
__device__ void do_fc(float* __restrict__ sA, float* __restrict__ sB, int tid,
                      const float* __restrict__ hin, const float* __restrict__ Wf,
                      const float* __restrict__ bf,
                      float* __restrict__ outp, long ldo, int bm, int bn,
                      int vmode, float* __restrict__ vfw)
{
    const int r2 = (tid >> 4) << 1;
    const int c2 = (tid & 15) << 1;
    float acc00 = 0.f, acc01 = 0.f, acc10 = 0.f, acc11 = 0.f;

    const int r = tid >> 3; const int kq = (tid & 7) << 2;
    float4 pa = *(const float4*)(hin + (long)(bm + r) * HID + kq);
    float4 pb = *(const float4*)(Wf + (long)(bn + r) * HID + kq);

    for (int k0 = 0; k0 < HID; k0 += 32) {
        __syncthreads();
        sA[(kq + 0) * 68 + r] = pa.x; sA[(kq + 1) * 68 + r] = pa.y;
        sA[(kq + 2) * 68 + r] = pa.z; sA[(kq + 3) * 68 + r] = pa.w;
        sB[(kq + 0) * 136 + r] = pb.x; sB[(kq + 1) * 136 + r] = pb.y;
        sB[(kq + 2) * 136 + r] = pb.z; sB[(kq + 3) * 136 + r] = pb.w;
        __syncthreads();

        int kn = k0 + 32;
        if (kn < HID) {
            pa = *(const float4*)(hin + (long)(bm + r) * HID + kn + kq);
            pb = *(const float4*)(Wf + (long)(bn + r) * HID + kn + kq);
        }

#pragma unroll
        for (int kk = 0; kk < 32; ++kk) {
            float a0 = sA[kk * 68 + r2], a1 = sA[kk * 68 + r2 + 1];
            float b0 = sB[kk * 136 + c2], b1 = sB[kk * 136 + c2 + 1];
            acc00 = fmaf(a0, b0, acc00); acc01 = fmaf(a0, b1, acc01);
            acc10 = fmaf(a1, b0, acc10); acc11 = fmaf(a1, b1, acc11);
        }
    }

    float o[2][2] = {{acc00 + bf[bn + c2], acc01 + bf[bn + c2 + 1]},
                     {acc10 + bf[bn + c2], acc11 + bf[bn + c2 + 1]}};

    if (vmode) {
#pragma unroll
        for (int rr = 0; rr < 2; ++rr) {
            int m = bm + r2 + rr;
            int MB = m >> 4, g = (m & 15) & 7, hf = (m >> 3) & 1;
#pragma unroll
            for (int jc = 0; jc < 2; ++jc) {
                int j = bn + c2 + jc;
                float val = o[rr][jc];
                float hi = tf32_rna(val);
                int c = j >> 5, kqf = (j >> 3) & 3, t = j & 3, kh = (j >> 2) & 1;
                long fo = (((long)(c * 4 + kqf) * 16 + MB) * 2) * 128
                          + (g * 4 + t) * 4 + kh * 2 + hf;
                vfw[fo]       = hi;
                vfw[fo + 128] = tf32_rna(val - hi);
            }
        }
    } else {
        *(float2*)(outp + (long)(bm + r2) * ldo + bn + c2)     = make_float2(o[0][0], o[0][1]);
        *(float2*)(outp + (long)(bm + r2 + 1) * ldo + bn + c2) = make_float2(o[1][0], o[1][1]);
    }
}

// ---------------------------------------------------------------------------
__global__ __launch_bounds__(256, 1) void bilstm_kernel(
    const float* __restrict__ wfc_l, const float* __restrict__ wfc_r,
    const float* __restrict__ bfc_l, const float* __restrict__ bfc_r,
    float* __restrict__ out)
{
    extern __shared__ __align__(16) char dyn[];
    __shared__ unsigned s_gen;

    const int tid = threadIdx.x;
    const int cid = blockIdx.x;
    const int dir = cid >> 6;
    const int idx = cid & 63;
    const int gbm = (idx >> 4) << 6;   // 4 M tiles of 64
    const int gbn = (idx & 15) << 7;   // 16 N tiles of 128
    const int fbm = (idx >> 3) << 5;
    const int fbn = (idx & 7) << 5;
    const int MB0 = gbm >> 4;
    const int NB0 = gbn >> 3;

    float* fcA = (float*)dyn;
    float* fcB = fcA + 32 * 68;

    if (tid == 0) s_gen = 0u;
    __syncthreads();

    const float* wfc = dir ? wfc_r : wfc_l;
    const float* bfc = dir ? bfc_r : bfc_l;

    for (int t = 0; t < T_STEPS; ++t) {
        const int p = t & 1;

        {   // gates depth 0 (A = x | h0)
            const int step = dir ? (T_STEPS - t) : t;
            gates_mma(dyn, tid,
                      &g_xf[step][0][0][MB0][0][0][0],
                      &g_hf[p][dir][0][0][0][MB0][0][0][0],
                      &g_wihF[dir][0][0][0][NB0][0][0],
                      &g_whhF[dir][0][0][0][NB0][0][0],
                      &g_biasR[dir][0][0],
                      &g_h[p ^ 1][dir][0][0][0], &g_c[dir][0][0][0],
                      &g_hf[p ^ 1][dir][0][0][0][0][0][0][0],
                      gbm, gbn);
        }
        grid_bar(&s_gen);

        do_fc(fcA, fcB, tid, &g_h[p ^ 1][dir][0][0][0], wfc, bfc,
              nullptr, 0, fbm, fbn, 1, &g_vf[dir][0][0][0][0][0][0]);
        grid_bar(&s_gen);

        {   // gates depth 1 (A = v | h1)
            gates_mma(dyn, tid,
                      &g_vf[dir][0][0][MB0][0][0][0],
                      &g_hf[p][dir][1][0][0][MB0][0][0][0],
                      &g_wihF[dir][1][0][0][NB0][0][0],
                      &g_whhF[dir][1][0][0][NB0][0][0],
                      &g_biasR[dir][1][0],
                      &g_h[p ^ 1][dir][1][0][0], &g_c[dir][1][0][0],
                      &g_hf[p ^ 1][dir][1][0][0][0][0][0][0],
                      gbm, gbn);
        }
        grid_bar(&s_gen);

        {   // fc depth 1 -> output
            const int tout = dir ? (T_STEPS + t) : t;
            do_fc(fcA, fcB, tid, &g_h[p ^ 1][dir][1][0][0],
                  wfc + (long)VEC * HID, bfc + VEC,
                  out + (long)tout * VEC, (long)2 * T_STEPS * VEC, fbm, fbn,
                  0, nullptr);
        }
        // no barrier: gates0(t+1) is independent of fc1(t).
    }
}

// ---------------------------------------------------------------------------
extern "C" void kernel_launch(void* const* d_in, const int* in_sizes, int n_in,
                              void* d_out, int out_size)
{
    const float* x     = (const float*)d_in[0];
    const float* wih_l = (const float*)d_in[1];
    const float* whh_l = (const float*)d_in[2];
    const float* bih_l = (const float*)d_in[3];
    const float* bhh_l = (const float*)d_in[4];
    const float* wfc_l = (const float*)d_in[5];
    const float* bfc_l = (const float*)d_in[6];
    const float* wih_r = (const float*)d_in[7];
    const float* whh_r = (const float*)d_in[8];
    const float* bih_r = (const float*)d_in[9];
    const float* bhh_r = (const float*)d_in[10];
    const float* wfc_r = (const float*)d_in[11];
    const float* bfc_r = (const float*)d_in[12];
    float* out = (float*)d_out;

    cudaFuncSetAttribute(bilstm_kernel,
                         cudaFuncAttributeMaxDynamicSharedMemorySize, SM_SZ);

    prep_kernel<<<512, 256>>>(x, wih_l, whh_l, bih_l, bhh_l,
                              wih_r, whh_r, bih_r, bhh_r);
    bilstm_kernel<<<NCTA, 256, SM_SZ>>>(wfc_l, wfc_r, bfc_l, bfc_r, out);
}